// round 4
// baseline (speedup 1.0000x reference)
#include <cuda_runtime.h>
#include <cstdint>

#define BB 256
#define PP 196
#define DD 512
#define AA 512
#define MM (BB*PP)   // 50176

// scratch (allocation-free rule: __device__ globals)
__device__ float g_hidden[BB*AA];   // hidden + bv  (for K2 epilogue)
__device__ float g_sh[BB*AA];       // st@Ws + bs + hidden (pre-tanh, for s_att)
__device__ float g_z[BB*PP];        // attention logits

__device__ __forceinline__ float tanh_fast(float x) {
    float e = __expf(2.0f * x);
    return 1.0f - 2.0f / (e + 1.0f);
}

__device__ __forceinline__ uint32_t f2tf(float x) {
    uint32_t r;
    asm("cvt.rna.tf32.f32 %0, %1;" : "=r"(r) : "f"(x));
    return r;
}

__device__ __forceinline__ uint2 split_tf(float x) {
    uint2 r;
    r.x = f2tf(x);
    r.y = f2tf(x - __uint_as_float(r.x));
    return r;
}

__device__ __forceinline__ void mma8(float* c, const uint32_t* a, const uint32_t* b) {
    asm volatile(
        "mma.sync.aligned.m16n8k8.row.col.f32.tf32.tf32.f32 "
        "{%0,%1,%2,%3}, {%4,%5,%6,%7}, {%8,%9}, {%0,%1,%2,%3};"
        : "+f"(c[0]), "+f"(c[1]), "+f"(c[2]), "+f"(c[3])
        : "r"(a[0]), "r"(a[1]), "r"(a[2]), "r"(a[3]), "r"(b[0]), "r"(b[1]));
}

// ---------------------------------------------------------------------------
// K1: hidden = dh@Wh + bh (stored +bv);  g_sh = st@Ws + bs + hidden (pre-tanh)
// grid (4 a-tiles, 32 b-tiles), 256 thr, tile 8b x 128a, BK=32.
// Thread = 2 batches x 2 a-cols (x2 matrices).
// ---------------------------------------------------------------------------
__global__ void __launch_bounds__(256) k_prep(
    const float* __restrict__ dh, const float* __restrict__ st,
    const float* __restrict__ Wh, const float* __restrict__ bh,
    const float* __restrict__ Ws, const float* __restrict__ bs,
    const float* __restrict__ bv)
{
    __shared__ float dh_s[8][33], st_s[8][33];
    __shared__ float Wh_s[32][128], Ws_s[32][128];
    const int tid = threadIdx.x;
    const int b0  = blockIdx.y * 8;
    const int a0  = blockIdx.x * 128;
    const int al  = (tid & 63) * 2;
    const int bl  = (tid >> 6) * 2;

    float acch[2][2] = {}, accs[2][2] = {};

    for (int kb = 0; kb < DD; kb += 32) {
        __syncthreads();
        {
            const int i  = tid;                  // 0..255 covers 8x32
            const int bb = i >> 5, kk = i & 31;
            dh_s[bb][kk] = dh[(b0 + bb)*DD + kb + kk];
            st_s[bb][kk] = st[(b0 + bb)*DD + kb + kk];
        }
        #pragma unroll
        for (int j = 0; j < 4; ++j) {
            const int i  = tid + j*256;          // f4 idx 0..1023
            const int kk = i >> 5, nq = i & 31;
            *(float4*)&Wh_s[kk][nq*4] = *(const float4*)&Wh[(size_t)(kb+kk)*AA + a0 + nq*4];
            *(float4*)&Ws_s[kk][nq*4] = *(const float4*)&Ws[(size_t)(kb+kk)*AA + a0 + nq*4];
        }
        __syncthreads();
        #pragma unroll 8
        for (int k = 0; k < 32; ++k) {
            const float2 wh = *(const float2*)&Wh_s[k][al];
            const float2 ws = *(const float2*)&Ws_s[k][al];
            #pragma unroll
            for (int bi = 0; bi < 2; ++bi) {
                const float dv = dh_s[bl+bi][k], sv = st_s[bl+bi][k];
                acch[bi][0] += dv*wh.x;  acch[bi][1] += dv*wh.y;
                accs[bi][0] += sv*ws.x;  accs[bi][1] += sv*ws.y;
            }
        }
    }
    #pragma unroll
    for (int bi = 0; bi < 2; ++bi)
        #pragma unroll
        for (int j = 0; j < 2; ++j) {
            const int b = b0 + bl + bi, a = a0 + al + j;
            const float h = acch[bi][j] + bh[a];
            g_hidden[(size_t)b*AA + a] = h + bv[a];
            g_sh[(size_t)b*AA + a]     = accs[bi][j] + bs[a] + h;
        }
}

// ---------------------------------------------------------------------------
// K2: z[m] = bav + sum_a Wav[a] * tanh( enc[m,:]@Wv[:,a] + hidden[b(m),a] )
// tf32 mma.sync, 3-pass split, hi/lo PRE-SPLIT at smem staging (uint2).
// Block tile 128x128, BK=32, 8 warps (4m x 2n), warp tile 32x64.
// ---------------------------------------------------------------------------
#define BM 128
#define BN 128
#define BK 32
#define APAD 36    // uint2 stride for A_s [BM][APAD]
#define BPAD 132   // uint2 stride for B_s [BK][BPAD]
#define K2_SMEM ((BM*APAD + BK*BPAD)*8 + (BN*3 + BM)*4 + 256)

__global__ void __launch_bounds__(256) k_zgemm(
    const float* __restrict__ enc, const float* __restrict__ Wv,
    const float* __restrict__ Wav, const float* __restrict__ bav)
{
    extern __shared__ unsigned char smem_raw[];
    uint2* A_s   = (uint2*)smem_raw;            // [BM][APAD]  (hi,lo)
    uint2* B_s   = A_s + BM*APAD;               // [BK][BPAD]  (hi,lo)
    float* wav_s = (float*)(B_s + BK*BPAD);     // [BN]
    float* h_s0  = wav_s + BN;                  // [BN]
    float* h_s1  = h_s0 + BN;                   // [BN]
    float* zs    = h_s1 + BN;                   // [BM]

    const int tid  = threadIdx.x, lane = tid & 31, wid = tid >> 5;
    const int wm   = wid & 3;          // m-warp 0..3
    const int wn   = wid >> 2;         // n-warp 0..1
    const int gid  = lane >> 2, tig = lane & 3;
    const int m0   = blockIdx.x * BM;
    const int b0   = m0 / PP;
    const int b1   = (m0 + BM - 1) / PP;
    const int bsplit = (b0 + 1) * PP;  // rows >= bsplit belong to b1

    if (tid < BM) zs[tid] = 0.f;

    for (int nt = 0; nt < 4; ++nt) {
        const int n0 = nt * BN;
        __syncthreads();  // protect h_s/wav_s from previous epilogue readers
        for (int i = tid; i < BN; i += 256) {
            wav_s[i] = Wav[n0 + i];
            h_s0[i]  = g_hidden[(size_t)b0*AA + n0 + i];
            h_s1[i]  = g_hidden[(size_t)b1*AA + n0 + i];
        }

        float acc[2][8][4];
        #pragma unroll
        for (int mi = 0; mi < 2; ++mi)
            #pragma unroll
            for (int ni = 0; ni < 8; ++ni)
                #pragma unroll
                for (int q = 0; q < 4; ++q) acc[mi][ni][q] = 0.f;

        // prefetch stage kb=0 into registers
        float4 pa[4], pb[4];
        #pragma unroll
        for (int j = 0; j < 4; ++j) {
            const int ia = tid + j*256;               // 0..1023
            pa[j] = *(const float4*)&enc[(size_t)(m0 + (ia>>3))*DD + (ia&7)*4];
            pb[j] = *(const float4*)&Wv[(size_t)(ia>>5)*AA + n0 + (ia&31)*4];
        }

        for (int kb = 0; kb < DD; kb += BK) {
            __syncthreads();
            #pragma unroll
            for (int j = 0; j < 4; ++j) {
                const int ia = tid + j*256;
                const int ar = ia >> 3,  ak = (ia & 7)*4;   // A row, k base
                const int bk = ia >> 5,  bn = (ia & 31)*4;  // B k,  n base
                const float av[4] = {pa[j].x, pa[j].y, pa[j].z, pa[j].w};
                const float bv4[4] = {pb[j].x, pb[j].y, pb[j].z, pb[j].w};
                #pragma unroll
                for (int q = 0; q < 4; ++q) {
                    A_s[ar*APAD + ak + q] = split_tf(av[q]);
                    B_s[bk*BPAD + bn + q] = split_tf(bv4[q]);
                }
            }
            __syncthreads();
            if (kb + BK < DD) {
                #pragma unroll
                for (int j = 0; j < 4; ++j) {
                    const int ia = tid + j*256;
                    pa[j] = *(const float4*)&enc[(size_t)(m0 + (ia>>3))*DD + kb + BK + (ia&7)*4];
                    pb[j] = *(const float4*)&Wv[(size_t)(kb + BK + (ia>>5))*AA + n0 + (ia&31)*4];
                }
            }
            #pragma unroll
            for (int k8 = 0; k8 < 4; ++k8) {
                const int kk = k8 * 8;
                uint32_t ah[2][4], al_[2][4], bh_[8][2], bl_[8][2];
                #pragma unroll
                for (int mi = 0; mi < 2; ++mi) {
                    const int r = wm*32 + mi*16 + gid;
                    const uint2 a0v = A_s[(r    )*APAD + kk + tig    ];
                    const uint2 a1v = A_s[(r + 8)*APAD + kk + tig    ];
                    const uint2 a2v = A_s[(r    )*APAD + kk + tig + 4];
                    const uint2 a3v = A_s[(r + 8)*APAD + kk + tig + 4];
                    ah[mi][0] = a0v.x; al_[mi][0] = a0v.y;
                    ah[mi][1] = a1v.x; al_[mi][1] = a1v.y;
                    ah[mi][2] = a2v.x; al_[mi][2] = a2v.y;
                    ah[mi][3] = a3v.x; al_[mi][3] = a3v.y;
                }
                #pragma unroll
                for (int ni = 0; ni < 8; ++ni) {
                    const int n = wn*64 + ni*8 + gid;
                    const uint2 b0v = B_s[(kk + tig    )*BPAD + n];
                    const uint2 b1v = B_s[(kk + tig + 4)*BPAD + n];
                    bh_[ni][0] = b0v.x; bl_[ni][0] = b0v.y;
                    bh_[ni][1] = b1v.x; bl_[ni][1] = b1v.y;
                }
                #pragma unroll
                for (int mi = 0; mi < 2; ++mi)
                    #pragma unroll
                    for (int ni = 0; ni < 8; ++ni) {
                        mma8(acc[mi][ni], ah[mi],  bh_[ni]);
                        mma8(acc[mi][ni], ah[mi],  bl_[ni]);
                        mma8(acc[mi][ni], al_[mi], bh_[ni]);
                    }
            }
        }

        // epilogue: tanh(v + hidden) * Wav, per-row partial sums
        float rs[2][2] = {0.f, 0.f, 0.f, 0.f};
        #pragma unroll
        for (int mi = 0; mi < 2; ++mi) {
            const int r_lo = m0 + wm*32 + mi*16 + gid;
            const float* hlo = (r_lo     >= bsplit) ? h_s1 : h_s0;
            const float* hhi = (r_lo + 8 >= bsplit) ? h_s1 : h_s0;
            #pragma unroll
            for (int ni = 0; ni < 8; ++ni) {
                const int c0 = wn*64 + ni*8 + 2*tig;
                const float w0 = wav_s[c0], w1 = wav_s[c0+1];
                rs[mi][0] += tanh_fast(acc[mi][ni][0] + hlo[c0  ]) * w0
                           + tanh_fast(acc[mi][ni][1] + hlo[c0+1]) * w1;
                rs[mi][1] += tanh_fast(acc[mi][ni][2] + hhi[c0  ]) * w0
                           + tanh_fast(acc[mi][ni][3] + hhi[c0+1]) * w1;
            }
        }
        #pragma unroll
        for (int off = 1; off <= 2; off <<= 1) {
            #pragma unroll
            for (int mi = 0; mi < 2; ++mi) {
                rs[mi][0] += __shfl_xor_sync(0xffffffffu, rs[mi][0], off);
                rs[mi][1] += __shfl_xor_sync(0xffffffffu, rs[mi][1], off);
            }
        }
        if (tig == 0) {
            #pragma unroll
            for (int mi = 0; mi < 2; ++mi) {
                atomicAdd(&zs[wm*32 + mi*16 + gid    ], rs[mi][0]);
                atomicAdd(&zs[wm*32 + mi*16 + gid + 8], rs[mi][1]);
            }
        }
    }
    __syncthreads();
    if (tid < BM) g_z[m0 + tid] = zs[tid] + bav[0];
}

// ---------------------------------------------------------------------------
// K3: s_att reduce; softmax(z) -> alpha; extended softmax -> beta;
//     c_t = enc^T alpha; c_hat = beta*st + (1-beta)*c_t
// grid (B, 2): each block owns 256 of the 512 d's of batch b.
// ---------------------------------------------------------------------------
__global__ void __launch_bounds__(256) k_soft(
    const float* __restrict__ enc, const float* __restrict__ st,
    const float* __restrict__ Was, const float* __restrict__ bas,
    float* __restrict__ out)
{
    __shared__ float zsh[PP];
    __shared__ float alpha_sh[PP];
    __shared__ float red[256];
    const int tid = threadIdx.x;
    const int b   = blockIdx.x;
    const int y   = blockIdx.y;

    // s_att[b] = sum_a tanh(g_sh[b,a]) * Was[a] + bas
    float sacc = 0.f;
    for (int i = tid; i < AA; i += 256)
        sacc += tanh_fast(g_sh[(size_t)b*AA + i]) * Was[i];
    red[tid] = sacc;
    __syncthreads();
    for (int s = 128; s > 0; s >>= 1) {
        if (tid < s) red[tid] += red[tid + s];
        __syncthreads();
    }
    const float sa = red[0] + bas[0];
    __syncthreads();

    if (tid < PP) zsh[tid] = g_z[b*PP + tid];
    __syncthreads();

    red[tid] = (tid < PP) ? zsh[tid] : -1e30f;
    __syncthreads();
    for (int s = 128; s > 0; s >>= 1) {
        if (tid < s) red[tid] = fmaxf(red[tid], red[tid + s]);
        __syncthreads();
    }
    const float m1 = red[0];
    __syncthreads();

    const float e = (tid < PP) ? __expf(zsh[tid] - m1) : 0.f;
    red[tid] = e;
    __syncthreads();
    for (int s = 128; s > 0; s >>= 1) {
        if (tid < s) red[tid] += red[tid + s];
        __syncthreads();
    }
    const float sum1 = red[0];

    if (tid < PP) {
        const float alpha = e / sum1;
        alpha_sh[tid] = alpha;
        if (y == 0) out[BB*DD + b*PP + tid] = alpha;     // alpha_t
    }

    const float m2   = fmaxf(m1, sa);
    const float sum2 = sum1 * __expf(m1 - m2) + __expf(sa - m2);
    const float beta = __expf(sa - m2) / sum2;
    if (y == 0 && tid == 0) out[BB*DD + BB*PP + b] = beta;  // beta_t
    __syncthreads();

    const int d = y*256 + tid;
    const float* ep = enc + (size_t)b*PP*DD + d;
    float acc = 0.f;
    #pragma unroll 8
    for (int p = 0; p < PP; ++p)
        acc += ep[(size_t)p*DD] * alpha_sh[p];

    out[b*DD + d] = beta * st[b*DD + d] + (1.f - beta) * acc;  // c_hat_t
}

// ---------------------------------------------------------------------------
extern "C" void kernel_launch(void* const* d_in, const int* in_sizes, int n_in,
                              void* d_out, int out_size) {
    const float* enc = (const float*)d_in[0];
    const float* dh  = (const float*)d_in[1];
    const float* st  = (const float*)d_in[2];
    const float* Wv  = (const float*)d_in[3];
    const float* bv  = (const float*)d_in[4];
    const float* Wh  = (const float*)d_in[5];
    const float* bh  = (const float*)d_in[6];
    const float* Ws  = (const float*)d_in[7];
    const float* bs  = (const float*)d_in[8];
    const float* Wav = (const float*)d_in[9];
    const float* bav = (const float*)d_in[10];
    const float* Was = (const float*)d_in[11];
    const float* bas = (const float*)d_in[12];
    float* out = (float*)d_out;

    static int smem_set = 0;
    if (!smem_set) {
        cudaFuncSetAttribute(k_zgemm,
            cudaFuncAttributeMaxDynamicSharedMemorySize, K2_SMEM);
        smem_set = 1;
    }

    k_prep <<<dim3(4, 32), 256>>>(dh, st, Wh, bh, Ws, bs, bv);
    k_zgemm<<<MM/BM, 256, K2_SMEM>>>(enc, Wv, Wav, bav);
    k_soft <<<dim3(BB, 2), 256>>>(enc, st, Was, bas, out);
}

// round 6
// speedup vs baseline: 2.0941x; 2.0941x over previous
#include <cuda_runtime.h>
#include <cuda_bf16.h>
#include <cstdint>

#define BB 256
#define PP 196
#define DD 512
#define AA 512
#define MM (BB*PP)   // 50176

// ---------------- scratch (__device__ globals; no allocs) -------------------
__device__ float g_hidden[BB*AA];      // hidden + bv
__device__ float g_sh[BB*AA];          // st@Ws + bs + hidden (pre-tanh)
__device__ float g_z[BB*PP];           // logits
// Wv^T split planes, fragment-packed: plane(0=hi,1=lo), n(512), 32 chunks x 4
// uint2 slots; slot t of chunk c = { bf16pair(k=16c+2t), bf16pair(k=16c+2t+8) }
__device__ uint4 g_WvP4[2*512*64];     // = 2*512*128 uint2, 1MB

// ---------------- helpers ---------------------------------------------------
__device__ __forceinline__ float tanhapx(float x) {
    float y; asm("tanh.approx.f32 %0, %1;" : "=f"(y) : "f"(x)); return y;
}

__device__ __forceinline__ void split2(float2 v, uint32_t& hi, uint32_t& lo) {
    __nv_bfloat16 hx = __float2bfloat16(v.x), hy = __float2bfloat16(v.y);
    __nv_bfloat16 lx = __float2bfloat16(v.x - __bfloat162float(hx));
    __nv_bfloat16 ly = __float2bfloat16(v.y - __bfloat162float(hy));
    hi = (uint32_t)__bfloat16_as_ushort(hx) | ((uint32_t)__bfloat16_as_ushort(hy) << 16);
    lo = (uint32_t)__bfloat16_as_ushort(lx) | ((uint32_t)__bfloat16_as_ushort(ly) << 16);
}

__device__ __forceinline__ void mma16(float* c, const uint32_t* a, const uint32_t* b) {
    asm volatile(
        "mma.sync.aligned.m16n8k16.row.col.f32.bf16.bf16.f32 "
        "{%0,%1,%2,%3}, {%4,%5,%6,%7}, {%8,%9}, {%0,%1,%2,%3};"
        : "+f"(c[0]), "+f"(c[1]), "+f"(c[2]), "+f"(c[3])
        : "r"(a[0]), "r"(a[1]), "r"(a[2]), "r"(a[3]), "r"(b[0]), "r"(b[1]));
}

// ---------------------------------------------------------------------------
// conv_wv: Wv[k][n] fp32 -> g_WvP4 packed bf16 hi/lo planes [n][k]
// grid 16 (32-n tiles), 256 threads; loops K in 64-chunks via transpose smem.
// ---------------------------------------------------------------------------
__global__ void __launch_bounds__(256) conv_wv(const float* __restrict__ Wv) {
    __shared__ float s[32][65];
    const int tid = threadIdx.x;
    const int n0  = blockIdx.x * 32;
    uint2* WvP2 = (uint2*)g_WvP4;

    for (int k0 = 0; k0 < DD; k0 += 64) {
        __syncthreads();
        #pragma unroll
        for (int j = 0; j < 8; ++j) {
            const int idx = tid + j*256;          // 32n x 64k
            const int k = idx >> 5, n = idx & 31;
            s[n][k] = Wv[(size_t)(k0 + k)*AA + n0 + n];
        }
        __syncthreads();
        #pragma unroll
        for (int j = 0; j < 4; ++j) {
            const int i = tid + j*256;            // 2 planes x 32n x 16 slots
            const int plane = i >> 9;
            const int r = i & 511;
            const int n = r >> 4, q = r & 15;
            const int c = q >> 2, t = q & 3;
            const int kl = c*16 + 2*t;
            uint32_t h0, l0, h1, l1;
            split2(make_float2(s[n][kl],   s[n][kl+1]), h0, l0);
            split2(make_float2(s[n][kl+8], s[n][kl+9]), h1, l1);
            uint2 w;
            w.x = plane ? l0 : h0;
            w.y = plane ? l1 : h1;
            WvP2[(size_t)plane*65536 + (size_t)(n0 + n)*128 + (k0/16 + c)*4 + t] = w;
        }
    }
}

// ---------------------------------------------------------------------------
// K1: hidden = dh@Wh + bh (+bv stored);  g_sh = st@Ws + bs + hidden
// grid (4 a-tiles x 64 b-tiles); tile 4b x 128a; BK=32.
// ---------------------------------------------------------------------------
__global__ void __launch_bounds__(256) k_prep(
    const float* __restrict__ dh, const float* __restrict__ st,
    const float* __restrict__ Wh, const float* __restrict__ bh,
    const float* __restrict__ Ws, const float* __restrict__ bs,
    const float* __restrict__ bv)
{
    __shared__ float dh_s[4][33], st_s[4][33];
    __shared__ float Wh_s[32][128], Ws_s[32][128];
    const int tid = threadIdx.x;
    const int b0  = blockIdx.y * 4;
    const int a0  = blockIdx.x * 128;
    const int al  = tid & 127;
    const int bl  = (tid >> 7) * 2;

    float acch[2] = {}, accs[2] = {};

    for (int kb = 0; kb < DD; kb += 32) {
        __syncthreads();
        if (tid < 128) {
            const int bb = tid >> 5, kk = tid & 31;
            dh_s[bb][kk] = dh[(b0 + bb)*DD + kb + kk];
            st_s[bb][kk] = st[(b0 + bb)*DD + kb + kk];
        }
        #pragma unroll
        for (int j = 0; j < 4; ++j) {
            const int i  = tid + j*256;
            const int kk = i >> 5, nq = i & 31;
            *(float4*)&Wh_s[kk][nq*4] = *(const float4*)&Wh[(size_t)(kb+kk)*AA + a0 + nq*4];
            *(float4*)&Ws_s[kk][nq*4] = *(const float4*)&Ws[(size_t)(kb+kk)*AA + a0 + nq*4];
        }
        __syncthreads();
        #pragma unroll 8
        for (int k = 0; k < 32; ++k) {
            const float wh = Wh_s[k][al], ws = Ws_s[k][al];
            #pragma unroll
            for (int bi = 0; bi < 2; ++bi) {
                acch[bi] += dh_s[bl+bi][k] * wh;
                accs[bi] += st_s[bl+bi][k] * ws;
            }
        }
    }
    #pragma unroll
    for (int bi = 0; bi < 2; ++bi) {
        const int b = b0 + bl + bi, a = a0 + al;
        const float h = acch[bi] + bh[a];
        g_hidden[(size_t)b*AA + a] = h + bv[a];
        g_sh[(size_t)b*AA + a]     = accs[bi] + bs[a] + h;
    }
}

// ---------------------------------------------------------------------------
// K2: z[m] = bav + sum_a Wav[a]*tanh( enc[m,:]@Wv[:,a] + hidden[b(m),a] )
// bf16 m16n8k16 mma.sync, 3-pass split, operands pre-packed in smem.
// BM=128, BN=256 (nt=2), BK=32; 512 thr / 16 warps (4m x 4n), warp 32x64.
// ---------------------------------------------------------------------------
#define ASTR 12              // uint2 per A row (8 used + 4 pad)
#define BSTR 12              // uint2 per B row
#define OFF_AH   0                    // 128*12*8  = 12288
#define OFF_AL   12288
#define OFF_BH   24576                // 256*12*8  = 24576
#define OFF_BL   49152
#define OFF_H0   73728                // 256 floats
#define OFF_H1   74752
#define OFF_WAV  75776
#define OFF_ZS   76800                // 128 floats
#define K2_SMEM  77312

__global__ void __launch_bounds__(512, 1) k_zgemm(
    const float* __restrict__ enc, const float* __restrict__ Wav,
    const float* __restrict__ bav)
{
    extern __shared__ unsigned char sm[];
    uint2* Ah   = (uint2*)(sm + OFF_AH);
    uint2* Al   = (uint2*)(sm + OFF_AL);
    uint2* Bh   = (uint2*)(sm + OFF_BH);
    uint2* Bl   = (uint2*)(sm + OFF_BL);
    float* h0s  = (float*)(sm + OFF_H0);
    float* h1s  = (float*)(sm + OFF_H1);
    float* wavs = (float*)(sm + OFF_WAV);
    float* zs   = (float*)(sm + OFF_ZS);

    const int tid  = threadIdx.x, lane = tid & 31, wid = tid >> 5;
    const int wm   = wid & 3;           // m-warp 0..3
    const int wn   = wid >> 2;          // n-warp 0..3
    const int gid  = lane >> 2, tig = lane & 3;
    const int m0   = blockIdx.x * 128;
    const int b0   = m0 / PP;
    const int b1   = (m0 + 127) / PP;
    const int bsplit = (b0 + 1) * PP;

    // A staging slot for this thread (2 slots)
    int sm_[2], sq_[2], skl_[2];
    #pragma unroll
    for (int j = 0; j < 2; ++j) {
        const int slot = tid + j*512;        // 0..1023 over 128m x 8q
        sm_[j]  = slot >> 3;
        sq_[j]  = slot & 7;
        skl_[j] = ((sq_[j] >> 2) << 4) + ((sq_[j] & 3) << 1);  // 16c + 2t
    }

    if (tid < 128) zs[tid] = 0.f;

    for (int nt = 0; nt < 2; ++nt) {
        const int n0 = nt * 256;
        __syncthreads();   // previous epilogue readers done
        for (int i = tid; i < 256; i += 512) {
            wavs[i] = Wav[n0 + i];
            h0s[i]  = g_hidden[(size_t)b0*AA + n0 + i];
            h1s[i]  = g_hidden[(size_t)b1*AA + n0 + i];
        }

        float acc[2][8][4];
        #pragma unroll
        for (int mi = 0; mi < 2; ++mi)
            #pragma unroll
            for (int ni = 0; ni < 8; ++ni)
                #pragma unroll
                for (int q = 0; q < 4; ++q) acc[mi][ni][q] = 0.f;

        // prefetch A stage kb=0
        float2 pa[2][2];
        #pragma unroll
        for (int j = 0; j < 2; ++j) {
            const float* base = &enc[(size_t)(m0 + sm_[j])*DD + skl_[j]];
            pa[j][0] = *(const float2*)(base);
            pa[j][1] = *(const float2*)(base + 8);
        }

        for (int kb = 0; kb < DD; kb += 32) {
            __syncthreads();   // previous compute done reading smem
            // ---- store A (split to bf16 hi/lo, fragment-packed) ----
            #pragma unroll
            for (int j = 0; j < 2; ++j) {
                uint32_t h0w, l0w, h1w, l1w;
                split2(pa[j][0], h0w, l0w);
                split2(pa[j][1], h1w, l1w);
                const int u = sm_[j]*ASTR + sq_[j];
                Ah[u] = make_uint2(h0w, h1w);
                Al[u] = make_uint2(l0w, l1w);
            }
            // ---- stage B: straight uint4 copies from packed planes ----
            #pragma unroll
            for (int j = 0; j < 4; ++j) {
                const int i = tid + j*512;        // 2 planes x 256n x 4 u4
                const int plane = i >> 10;
                const int r = i & 1023;
                const int n = r >> 2, s4 = r & 3;
                const uint4 v = g_WvP4[(size_t)plane*32768 +
                                       (size_t)(n0 + n)*64 + (kb >> 4)*2 + s4];
                uint4* dst = (uint4*)(plane ? (void*)Bl : (void*)Bh);
                dst[n*(BSTR/2) + s4] = v;
            }
            __syncthreads();
            // ---- prefetch next A stage ----
            if (kb + 32 < DD) {
                #pragma unroll
                for (int j = 0; j < 2; ++j) {
                    const float* base =
                        &enc[(size_t)(m0 + sm_[j])*DD + kb + 32 + skl_[j]];
                    pa[j][0] = *(const float2*)(base);
                    pa[j][1] = *(const float2*)(base + 8);
                }
            }
            // ---- compute: 2 k16 steps ----
            #pragma unroll
            for (int c = 0; c < 2; ++c) {
                uint32_t ah[2][4], alo[2][4];
                #pragma unroll
                for (int mi = 0; mi < 2; ++mi) {
                    const int r = wm*32 + mi*16 + gid;
                    const uint2 u0 = Ah[(r    )*ASTR + c*4 + tig];
                    const uint2 u1 = Ah[(r + 8)*ASTR + c*4 + tig];
                    ah[mi][0] = u0.x; ah[mi][1] = u1.x;
                    ah[mi][2] = u0.y; ah[mi][3] = u1.y;
                    const uint2 v0 = Al[(r    )*ASTR + c*4 + tig];
                    const uint2 v1 = Al[(r + 8)*ASTR + c*4 + tig];
                    alo[mi][0] = v0.x; alo[mi][1] = v1.x;
                    alo[mi][2] = v0.y; alo[mi][3] = v1.y;
                }
                #pragma unroll
                for (int ni = 0; ni < 8; ++ni) {
                    const int n = wn*64 + ni*8 + gid;
                    const uint2 ubh = Bh[n*BSTR + c*4 + tig];
                    const uint2 ubl = Bl[n*BSTR + c*4 + tig];
                    const uint32_t bhf[2] = {ubh.x, ubh.y};
                    const uint32_t blf[2] = {ubl.x, ubl.y};
                    #pragma unroll
                    for (int mi = 0; mi < 2; ++mi) {
                        mma16(acc[mi][ni], ah[mi],  bhf);
                        mma16(acc[mi][ni], ah[mi],  blf);
                        mma16(acc[mi][ni], alo[mi], bhf);
                    }
                }
            }
        }

        // ---- epilogue: tanh(v + hidden) * Wav, row partial sums ----
        float rs[2][2] = {0.f, 0.f, 0.f, 0.f};
        #pragma unroll
        for (int mi = 0; mi < 2; ++mi) {
            const int r_lo = m0 + wm*32 + mi*16 + gid;
            const float* hlo = (r_lo     >= bsplit) ? h1s : h0s;
            const float* hhi = (r_lo + 8 >= bsplit) ? h1s : h0s;
            #pragma unroll
            for (int ni = 0; ni < 8; ++ni) {
                const int c0 = wn*64 + ni*8 + 2*tig;
                const float w0 = wavs[c0], w1 = wavs[c0+1];
                rs[mi][0] += tanhapx(acc[mi][ni][0] + hlo[c0  ]) * w0
                           + tanhapx(acc[mi][ni][1] + hlo[c0+1]) * w1;
                rs[mi][1] += tanhapx(acc[mi][ni][2] + hhi[c0  ]) * w0
                           + tanhapx(acc[mi][ni][3] + hhi[c0+1]) * w1;
            }
        }
        #pragma unroll
        for (int off = 1; off <= 2; off <<= 1) {
            #pragma unroll
            for (int mi = 0; mi < 2; ++mi) {
                rs[mi][0] += __shfl_xor_sync(0xffffffffu, rs[mi][0], off);
                rs[mi][1] += __shfl_xor_sync(0xffffffffu, rs[mi][1], off);
            }
        }
        if (tig == 0) {
            #pragma unroll
            for (int mi = 0; mi < 2; ++mi) {
                atomicAdd(&zs[wm*32 + mi*16 + gid    ], rs[mi][0]);
                atomicAdd(&zs[wm*32 + mi*16 + gid + 8], rs[mi][1]);
            }
        }
    }
    __syncthreads();
    if (tid < 128) g_z[m0 + tid] = zs[tid] + bav[0];
}

// ---------------------------------------------------------------------------
// K3: s_att reduce; softmax; beta; c_t; gated output
// ---------------------------------------------------------------------------
__global__ void __launch_bounds__(256) k_soft(
    const float* __restrict__ enc, const float* __restrict__ st,
    const float* __restrict__ Was, const float* __restrict__ bas,
    float* __restrict__ out)
{
    __shared__ float zsh[PP];
    __shared__ float alpha_sh[PP];
    __shared__ float red[256];
    const int tid = threadIdx.x;
    const int b   = blockIdx.x;
    const int y   = blockIdx.y;

    float sacc = 0.f;
    for (int i = tid; i < AA; i += 256)
        sacc += tanhapx(g_sh[(size_t)b*AA + i]) * Was[i];
    red[tid] = sacc;
    __syncthreads();
    for (int s = 128; s > 0; s >>= 1) {
        if (tid < s) red[tid] += red[tid + s];
        __syncthreads();
    }
    const float sa = red[0] + bas[0];
    __syncthreads();

    if (tid < PP) zsh[tid] = g_z[b*PP + tid];
    __syncthreads();

    red[tid] = (tid < PP) ? zsh[tid] : -1e30f;
    __syncthreads();
    for (int s = 128; s > 0; s >>= 1) {
        if (tid < s) red[tid] = fmaxf(red[tid], red[tid + s]);
        __syncthreads();
    }
    const float m1 = red[0];
    __syncthreads();

    const float e = (tid < PP) ? __expf(zsh[tid] - m1) : 0.f;
    red[tid] = e;
    __syncthreads();
    for (int s = 128; s > 0; s >>= 1) {
        if (tid < s) red[tid] += red[tid + s];
        __syncthreads();
    }
    const float sum1 = red[0];

    if (tid < PP) {
        const float alpha = e / sum1;
        alpha_sh[tid] = alpha;
        if (y == 0) out[BB*DD + b*PP + tid] = alpha;     // alpha_t
    }

    const float m2   = fmaxf(m1, sa);
    const float sum2 = sum1 * __expf(m1 - m2) + __expf(sa - m2);
    const float beta = __expf(sa - m2) / sum2;
    if (y == 0 && tid == 0) out[BB*DD + BB*PP + b] = beta;  // beta_t
    __syncthreads();

    const int d = y*256 + tid;
    const float* ep = enc + (size_t)b*PP*DD + d;
    float acc = 0.f;
    #pragma unroll 8
    for (int p = 0; p < PP; ++p)
        acc += ep[(size_t)p*DD] * alpha_sh[p];

    out[b*DD + d] = beta * st[b*DD + d] + (1.f - beta) * acc;  // c_hat_t
}

// ---------------------------------------------------------------------------
extern "C" void kernel_launch(void* const* d_in, const int* in_sizes, int n_in,
                              void* d_out, int out_size) {
    const float* enc = (const float*)d_in[0];
    const float* dh  = (const float*)d_in[1];
    const float* st  = (const float*)d_in[2];
    const float* Wv  = (const float*)d_in[3];
    const float* bv  = (const float*)d_in[4];
    const float* Wh  = (const float*)d_in[5];
    const float* bh  = (const float*)d_in[6];
    const float* Ws  = (const float*)d_in[7];
    const float* bs  = (const float*)d_in[8];
    const float* Wav = (const float*)d_in[9];
    const float* bav = (const float*)d_in[10];
    const float* Was = (const float*)d_in[11];
    const float* bas = (const float*)d_in[12];
    float* out = (float*)d_out;

    static int smem_set = 0;
    if (!smem_set) {
        cudaFuncSetAttribute(k_zgemm,
            cudaFuncAttributeMaxDynamicSharedMemorySize, K2_SMEM);
        smem_set = 1;
    }

    conv_wv<<<16, 256>>>(Wv);
    k_prep <<<dim3(4, 64), 256>>>(dh, st, Wh, bh, Ws, bs, bv);
    k_zgemm<<<MM/128, 512, K2_SMEM>>>(enc, Wav, bav);
    k_soft <<<dim3(BB, 2), 256>>>(enc, st, Was, bas, out);
}